// round 7
// baseline (speedup 1.0000x reference)
#include <cuda_runtime.h>

// Problem constants (fixed by the dataset)
#define BSZ   16384
#define KNUM  1000
#define DIMN  768

#define THREADS 256            // 8 warps = 4 sample-pairs per block
#define PAIRS_PER_BLOCK 4
#define BLOCKS (BSZ / PAIRS_PER_BLOCK)   // 4096

#define ROW_V4   (DIMN / 4)    // 192 float4 per row
#define HALF_V4  3             // per-lane float4 in a half-row: 96/32
#define MASK_V4  (KNUM / 4)    // 250

__device__ __forceinline__ float4 ldcs4(const float4* p) {
    float4 v;
    asm volatile("ld.global.cs.v4.f32 {%0,%1,%2,%3}, [%4];"
                 : "=f"(v.x), "=f"(v.y), "=f"(v.z), "=f"(v.w) : "l"(p));
    return v;
}
__device__ __forceinline__ void stcs4(float4* p, float4 v) {
    asm volatile("st.global.cs.v4.f32 [%0], {%1,%2,%3,%4};"
                 :: "l"(p), "f"(v.x), "f"(v.y), "f"(v.z), "f"(v.w));
}
__device__ __forceinline__ void pair_bar(int pair) {
    // 2-warp barrier per sample pair; ids 1..4 (0 left for __syncthreads)
    asm volatile("bar.sync %0, 64;" :: "r"(pair + 1) : "memory");
}

__global__ __launch_bounds__(THREADS, 4)
void css_kernel(const float* __restrict__ mask,   // [BS, K]
                const float* __restrict__ z,      // [BS, DIM]
                const float* __restrict__ S,      // [K, 2*DIM]
                const float* __restrict__ A,      // [K, 2]
                const float* __restrict__ LG,     // [K, 2]
                float* __restrict__ out)          // [BS, DIM]
{
    __shared__ float sh_acc[PAIRS_PER_BLOCK][2];
    __shared__ float sh_dot[PAIRS_PER_BLOCK][2][6];

    const int tid  = threadIdx.x;
    const int warp = tid >> 5;
    const int lane = tid & 31;
    const int pair = warp >> 1;          // 0..3  : sample within block
    const int w    = warp & 1;           // 0/1   : which half of the row
    const int smp  = blockIdx.x * PAIRS_PER_BLOCK + pair;

    // ---- 1. Half mask scan: idx = sum_k mask[k]*k (exact: entries 0/1)
    //         warp w covers float4 indices [128w, 128w+128) ∩ [0,250)
    const float4* __restrict__ mrow =
        reinterpret_cast<const float4*>(mask + (size_t)smp * KNUM);
    float acc = 0.0f;
    #pragma unroll
    for (int it = 0; it < 4; it++) {
        int i = 128 * w + lane + 32 * it;
        if (i < MASK_V4) {
            float4 v = ldcs4(&mrow[i]);
            float b = (float)(4 * i);
            acc = fmaf(v.x, b,        acc);
            acc = fmaf(v.y, b + 1.0f, acc);
            acc = fmaf(v.z, b + 2.0f, acc);
            acc = fmaf(v.w, b + 3.0f, acc);
        }
    }

    // ---- 2. z half-row loads (independent of idx; hide under reduction)
    const float4* __restrict__ zrow =
        reinterpret_cast<const float4*>(z + (size_t)smp * DIMN);
    const int base = w * (ROW_V4 / 2);   // 0 or 96
    float4 zr[HALF_V4];
    #pragma unroll
    for (int i = 0; i < HALF_V4; i++)
        zr[i] = ldcs4(&zrow[base + lane + 32 * i]);

    // warp partial reduce + cross-warp combine for idx
    #pragma unroll
    for (int o = 16; o > 0; o >>= 1)
        acc += __shfl_xor_sync(0xffffffffu, acc, o);
    if (lane == 0) sh_acc[pair][w] = acc;
    pair_bar(pair);
    const int idx = __float2int_rn(sh_acc[pair][0] + sh_acc[pair][1]);

    // ---- 3. Dipole scalars + S half-row gathers
    const float2 Av = __ldg(reinterpret_cast<const float2*>(A)  + idx);
    const float2 Lv = __ldg(reinterpret_cast<const float2*>(LG) + idx);
    const float g0 = __expf(Lv.x), g1 = __expf(Lv.y);

    const float4* __restrict__ s0p =
        reinterpret_cast<const float4*>(S + (size_t)idx * (2 * DIMN));
    const float4* __restrict__ s1p = s0p + ROW_V4;

    float4 s0r[HALF_V4], s1r[HALF_V4];
    #pragma unroll
    for (int i = 0; i < HALF_V4; i++) {
        const int p = base + lane + 32 * i;
        s0r[i] = __ldg(&s0p[p]);
        s1r[i] = __ldg(&s1p[p]);
    }

    // ---- 4. Six partial dot products over the half-row
    float zz = 0.f, ss0 = 0.f, ss1 = 0.f, c0 = 0.f, c1 = 0.f, s01 = 0.f;
    #pragma unroll
    for (int i = 0; i < HALF_V4; i++) {
        float4 zv = zr[i], s0 = s0r[i], s1 = s1r[i];
        zz  = fmaf(zv.x, zv.x, zz);   zz  = fmaf(zv.y, zv.y, zz);
        zz  = fmaf(zv.z, zv.z, zz);   zz  = fmaf(zv.w, zv.w, zz);
        ss0 = fmaf(s0.x, s0.x, ss0);  ss0 = fmaf(s0.y, s0.y, ss0);
        ss0 = fmaf(s0.z, s0.z, ss0);  ss0 = fmaf(s0.w, s0.w, ss0);
        ss1 = fmaf(s1.x, s1.x, ss1);  ss1 = fmaf(s1.y, s1.y, ss1);
        ss1 = fmaf(s1.z, s1.z, ss1);  ss1 = fmaf(s1.w, s1.w, ss1);
        c0  = fmaf(zv.x, s0.x, c0);   c0  = fmaf(zv.y, s0.y, c0);
        c0  = fmaf(zv.z, s0.z, c0);   c0  = fmaf(zv.w, s0.w, c0);
        c1  = fmaf(zv.x, s1.x, c1);   c1  = fmaf(zv.y, s1.y, c1);
        c1  = fmaf(zv.z, s1.z, c1);   c1  = fmaf(zv.w, s1.w, c1);
        s01 = fmaf(s0.x, s1.x, s01);  s01 = fmaf(s0.y, s1.y, s01);
        s01 = fmaf(s0.z, s1.z, s01);  s01 = fmaf(s0.w, s1.w, s01);
    }
    #pragma unroll
    for (int o = 16; o > 0; o >>= 1) {
        zz  += __shfl_xor_sync(0xffffffffu, zz,  o);
        ss0 += __shfl_xor_sync(0xffffffffu, ss0, o);
        ss1 += __shfl_xor_sync(0xffffffffu, ss1, o);
        c0  += __shfl_xor_sync(0xffffffffu, c0,  o);
        c1  += __shfl_xor_sync(0xffffffffu, c1,  o);
        s01 += __shfl_xor_sync(0xffffffffu, s01, o);
    }
    if (lane == 0) {
        sh_dot[pair][w][0] = zz;   sh_dot[pair][w][1] = ss0;
        sh_dot[pair][w][2] = ss1;  sh_dot[pair][w][3] = c0;
        sh_dot[pair][w][4] = c1;   sh_dot[pair][w][5] = s01;
    }
    pair_bar(pair);
    zz  = sh_dot[pair][0][0] + sh_dot[pair][1][0];
    ss0 = sh_dot[pair][0][1] + sh_dot[pair][1][1];
    ss1 = sh_dot[pair][0][2] + sh_dot[pair][1][2];
    c0  = sh_dot[pair][0][3] + sh_dot[pair][1][3];
    c1  = sh_dot[pair][0][4] + sh_dot[pair][1][4];
    s01 = sh_dot[pair][0][5] + sh_dot[pair][1][5];

    // ---- 5. Scalar algebra (duplicated in both warps; trivial)
    const float sq0 = zz - 2.0f * c0 + ss0;
    const float sq1 = zz - 2.0f * c1 + ss1;
    const float w0  = -2.0f * Av.x * g0 * __expf(-g0 * sq0);
    const float w1  = -2.0f * Av.y * g1 * __expf(-g1 * sq1);
    const float W   = w0 + w1;
    const float zg  = W * zz - w0 * c0 - w1 * c1;    // z . grad
    const float beta = W - zg;                       // proj = beta z - w0 s0 - w1 s1
    const float nrm2 = beta * beta * zz
                     + w0 * w0 * ss0
                     + w1 * w1 * ss1
                     - 2.0f * beta * w0 * c0
                     - 2.0f * beta * w1 * c1
                     + 2.0f * w0 * w1 * s01;
    const float inv = rsqrtf(nrm2);
    const float bz = beta * inv;
    const float b0 = -w0 * inv;
    const float b1 = -w1 * inv;

    // ---- 6. Epilogue: register-only combine, streamed stores (half-row)
    float4* __restrict__ orow =
        reinterpret_cast<float4*>(out + (size_t)smp * DIMN);
    #pragma unroll
    for (int i = 0; i < HALF_V4; i++) {
        float4 o4;
        o4.x = fmaf(bz, zr[i].x, fmaf(b0, s0r[i].x, b1 * s1r[i].x));
        o4.y = fmaf(bz, zr[i].y, fmaf(b0, s0r[i].y, b1 * s1r[i].y));
        o4.z = fmaf(bz, zr[i].z, fmaf(b0, s0r[i].z, b1 * s1r[i].z));
        o4.w = fmaf(bz, zr[i].w, fmaf(b0, s0r[i].w, b1 * s1r[i].w));
        stcs4(&orow[base + lane + 32 * i], o4);
    }
}

extern "C" void kernel_launch(void* const* d_in, const int* in_sizes, int n_in,
                              void* d_out, int out_size)
{
    const float* mask = (const float*)d_in[0];   // [BS, K]
    const float* z    = (const float*)d_in[1];   // [BS, DIM]
    const float* S    = (const float*)d_in[2];   // [K, 2*DIM]
    const float* A    = (const float*)d_in[3];   // [K, 2]
    const float* LG   = (const float*)d_in[4];   // [K, 2]
    float* out        = (float*)d_out;           // [BS, DIM]

    css_kernel<<<BLOCKS, THREADS>>>(mask, z, S, A, LG, out);
}